// round 16
// baseline (speedup 1.0000x reference)
#include <cuda_runtime.h>
#include <cuda_bf16.h>
#include <cuda_fp16.h>
#include <cstdint>

// Problem constants
#define BB 4
#define NT 1568
#define NH 16
#define HD 64
#define CC 1024
#define MROWS (BB * NT)          // 6272

// ---------------------------------------------------------------------------
// Scratch (device globals — no allocations allowed)
// ---------------------------------------------------------------------------
static __device__ __align__(16) float g_ctab[NT * 60];
static __device__ __align__(16) float g_stab[NT * 60];
static __device__ __align__(16) __half g_xf[MROWS * CC];
static __device__ __align__(16) __half g_wqf[3 * CC * CC];
static __device__ __align__(16) __half g_wpf[CC * CC];
#define QKVN (BB * NH * NT * HD)
static __device__ __align__(16) __half g_qf[QKVN], g_kf[QKVN], g_vf[QKVN];
static __device__ __align__(16) __half g_of[MROWS * CC];

#define LOG2E 1.44269504088896340736f

// ---------------------------------------------------------------------------
// Baseline-PTX helpers (plain sm_100 target)
// ---------------------------------------------------------------------------
__device__ __forceinline__ uint32_t smem_u32(const void* p) {
    uint32_t a;
    asm("{ .reg .u64 t; cvta.to.shared.u64 t, %1; cvt.u32.u64 %0, t; }" : "=r"(a) : "l"(p));
    return a;
}
__device__ __forceinline__ void ldm4(uint32_t* r, uint32_t addr) {
    asm volatile("ldmatrix.sync.aligned.m8n8.x4.shared.b16 {%0,%1,%2,%3}, [%4];"
                 : "=r"(r[0]), "=r"(r[1]), "=r"(r[2]), "=r"(r[3]) : "r"(addr));
}
__device__ __forceinline__ void ldm4t(uint32_t* r, uint32_t addr) {
    asm volatile("ldmatrix.sync.aligned.m8n8.x4.trans.shared.b16 {%0,%1,%2,%3}, [%4];"
                 : "=r"(r[0]), "=r"(r[1]), "=r"(r[2]), "=r"(r[3]) : "r"(addr));
}
__device__ __forceinline__ void mma16816h(float* c, const uint32_t* a, const uint32_t* b) {
    asm volatile(
        "mma.sync.aligned.m16n8k16.row.col.f32.f16.f16.f32 "
        "{%0,%1,%2,%3}, {%4,%5,%6,%7}, {%8,%9}, {%0,%1,%2,%3};"
        : "+f"(c[0]), "+f"(c[1]), "+f"(c[2]), "+f"(c[3])
        : "r"(a[0]), "r"(a[1]), "r"(a[2]), "r"(a[3]), "r"(b[0]), "r"(b[1]));
}
__device__ __forceinline__ void cp16(uint32_t s, const void* g) {
    asm volatile("cp.async.cg.shared.global [%0], [%1], 16;" :: "r"(s), "l"(g));
}
__device__ __forceinline__ void cp16z(uint32_t s, const void* g, int sz) {
    asm volatile("cp.async.cg.shared.global [%0], [%1], 16, %2;" :: "r"(s), "l"(g), "r"(sz));
}
#define CP_COMMIT() asm volatile("cp.async.commit_group;" ::: "memory")
#define CP_WAIT(n)  asm volatile("cp.async.wait_group %0;" :: "n"(n) : "memory")

__device__ __forceinline__ uint32_t pack_h2(float a, float b) {
    __half2 v = __floats2half2_rn(a, b);
    return *(uint32_t*)&v;
}
__device__ __forceinline__ float ex2(float x) {
    float y;
    asm("ex2.approx.f32 %0, %1;" : "=f"(y) : "f"(x));
    return y;
}
__device__ __forceinline__ uint32_t ex2h2(uint32_t x) {
    uint32_t y;
    asm("ex2.approx.f16x2 %0, %1;" : "=r"(y) : "r"(x));
    return y;
}

// ---------------------------------------------------------------------------
// RoPE table (validated R4/R6)
// ---------------------------------------------------------------------------
__global__ void rope_tab_k() {
    int i = blockIdx.x * 256 + threadIdx.x;
    if (i >= NT * 60) return;
    int n = i / 60;
    int d = i - n * 60;
    int axis = d / 20;
    int fi = (d % 20) % 10;
    int fr = n / 196;
    int inf = n - fr * 196;
    int hh = inf / 14;
    int ww = inf - hh * 14;
    float pos = (axis == 0) ? (float)fr : ((axis == 1) ? (float)hh : (float)ww);
    float omega = 1.0f / powf(10000.0f, (float)fi * 0.1f);
    g_ctab[i] = cosf(pos * omega);
    g_stab[i] = sinf(pos * omega);
}

// ---------------------------------------------------------------------------
// Fused fp32 -> fp16 conversion of x, Wqkv, Wproj in one launch (grid-stride)
// ---------------------------------------------------------------------------
#define N4X (MROWS * CC / 4)       // 1605632
#define N4W (3 * CC * CC / 4)      //  786432
#define N4P (CC * CC / 4)          //  262144
#define N4ALL (N4X + N4W + N4P)

__global__ void conv_all_k(const float* __restrict__ x,
                           const float* __restrict__ wq,
                           const float* __restrict__ wp) {
    for (int i = blockIdx.x * 256 + threadIdx.x; i < N4ALL; i += gridDim.x * 256) {
        const float* s;
        __half* d;
        int j = i;
        if (j < N4X) { s = x; d = g_xf; }
        else if (j < N4X + N4W) { j -= N4X; s = wq; d = g_wqf; }
        else { j -= N4X + N4W; s = wp; d = g_wpf; }
        float4 v = ((const float4*)s)[j];
        ((uint32_t*)d)[2 * j]     = pack_h2(v.x, v.y);
        ((uint32_t*)d)[2 * j + 1] = pack_h2(v.z, v.w);
    }
}

// ---------------------------------------------------------------------------
// mma.sync fp16 GEMM, cp.async double buffer, ONE sync per stage (validated R13).
// EPI 0: QKV + RoPE -> fp16 q/k/v (q pre-scaled 0.125*log2e). grid 24x49
// EPI 1: out-projection + bias -> Cout.                       grid  8x49
// ---------------------------------------------------------------------------
#define TILE_B 10240
#define STG_B (2 * TILE_B)
#define OFF_A 0
#define OFF_B (TILE_B)
#define GEMM_SMEM (2 * STG_B)        // 40960 B

template <int EPI>
__global__ __launch_bounds__(256, 2) void gemm_mma(
    float* __restrict__ Cout, const float* __restrict__ bias)
{
    extern __shared__ __align__(16) char sm[];
    const uint32_t sb = smem_u32(sm);

    const int tid = threadIdx.x;
    const int lane = tid & 31;
    const int wid = tid >> 5;
    const int wm = wid & 3;
    const int wn = wid >> 2;
    const int bx = blockIdx.x;
    const int by = blockIdx.y;

    const __half* Ag = (EPI == 0) ? g_xf : g_of;
    const __half* Bg = (EPI == 0) ? g_wqf : g_wpf;

    float acc[2][8][4];
#pragma unroll
    for (int mi = 0; mi < 2; mi++)
#pragma unroll
        for (int ni = 0; ni < 8; ni++)
#pragma unroll
            for (int j = 0; j < 4; j++) acc[mi][ni][j] = 0.0f;

    const int lrow = tid >> 2;
    const int lch = tid & 3;
    const uint32_t a_off = (uint32_t)(((wm * 32 + (lane & 15)) * 40 + ((lane >> 4) << 3)) * 2);
    const uint32_t b_off = (uint32_t)(((wn * 64 + (lane & 7) + ((lane >> 4) << 3)) * 40 +
                                      (((lane >> 3) & 1) << 3)) * 2);

    auto issue_tile = [&](int s, int buf) {
        const int k0 = s * 32;
        const uint32_t bbs = sb + buf * STG_B;
#pragma unroll
        for (int hh = 0; hh < 2; hh++) {
            int r = lrow + hh * 64;
            size_t ga = (size_t)(by * 128 + r) * 1024 + k0 + lch * 8;
            size_t gb = (size_t)(bx * 128 + r) * 1024 + k0 + lch * 8;
            uint32_t so = bbs + (uint32_t)((r * 40 + lch * 8) * 2);
            cp16(so + OFF_A, Ag + ga);
            cp16(so + OFF_B, Bg + gb);
        }
    };

    issue_tile(0, 0);
    CP_COMMIT();

#pragma unroll 1
    for (int s = 0; s < 32; s++) {
        CP_WAIT(0);
        __syncthreads();             // stage-s data visible; all threads done with s-1
        if (s + 1 < 32) {
            issue_tile(s + 1, (s + 1) & 1);   // overlaps compute of stage s
            CP_COMMIT();
        }

        const uint32_t bbs = sb + (s & 1) * STG_B;
#pragma unroll
        for (int ks = 0; ks < 2; ks++) {
            const uint32_t kb = (uint32_t)(ks * 32);
            uint32_t af[2][4];
            ldm4(af[0], bbs + OFF_A + a_off + kb);
            ldm4(af[1], bbs + OFF_A + a_off + kb + 16 * 80);
#pragma unroll
            for (int np = 0; np < 4; np++) {
                uint32_t bf[4];
                ldm4(bf, bbs + OFF_B + b_off + kb + np * 16 * 80);
#pragma unroll
                for (int mi = 0; mi < 2; mi++) {
                    mma16816h(acc[mi][2 * np],     af[mi], bf);
                    mma16816h(acc[mi][2 * np + 1], af[mi], bf + 2);
                }
            }
        }
    }

    const int g = lane >> 2;
    const int t = lane & 3;
#pragma unroll
    for (int mi = 0; mi < 2; mi++) {
#pragma unroll
        for (int ni = 0; ni < 8; ni++) {
#pragma unroll
            for (int half = 0; half < 2; half++) {
                int rr = wm * 32 + mi * 16 + g + half * 8;
                int o = bx * 128 + wn * 64 + ni * 8 + 2 * t;
                float e = acc[mi][ni][2 * half];
                float oo = acc[mi][ni][2 * half + 1];
                int m = by * 128 + rr;
                if (EPI == 0) {
                    int b = m / NT;
                    int n = m - b * NT;
                    int nb = n * 60;
                    int sidx = o >> 10;
                    int hd = (o & 1023) >> 6;
                    int d = o & 63;
                    float oe = e, of = oo;
                    if (sidx < 2 && d < 60) {
                        float c0 = g_ctab[nb + d],     s0 = g_stab[nb + d];
                        float c1 = g_ctab[nb + d + 1], s1 = g_stab[nb + d + 1];
                        oe = fmaf(e, c0, -oo * s0);
                        of = fmaf(oo, c1, e * s1);
                    }
                    if (sidx == 0) { oe *= 0.125f * LOG2E; of *= 0.125f * LOG2E; }
                    __half* df = (sidx == 0) ? g_qf : ((sidx == 1) ? g_kf : g_vf);
                    size_t base = ((size_t)((b * NH + hd) * NT + n)) * 64 + d;
                    *(uint32_t*)&df[base] = pack_h2(oe, of);
                } else {
                    float2 bv = *(const float2*)&bias[o];
                    *(float2*)&Cout[(size_t)m * CC + o] = make_float2(e + bv.x, oo + bv.y);
                }
            }
        }
    }
}

// ---------------------------------------------------------------------------
// fp16 tensor-core flash attention, software-pipelined S:
//   softmax(S_kt) -> P frags -> compute S_{kt+1} (indep of softmax) -> PV(kt)
// 3-stage cp.async KV ring; Q fragments register-resident; base-2 softmax
// with fp16x2 exp; row-sum l via ones-column MMA.
// grid (13 q-tiles, 64 bh). BQ=128, BK=64, 8 warps x m16 rows.
// ---------------------------------------------------------------------------
#define AST 72
#define QF_B 0
#define KV0_B (128 * AST * 2)            // 18432
#define KVSTG_B (2 * 64 * AST * 2)       // 18432
#define V_B (64 * AST * 2)               // 9216
#define ATTN_SMEM (KV0_B + 3 * KVSTG_B)  // 73728 bytes

#define ONES_H2 0x3C003C00u              // half2(1.0, 1.0)

__global__ __launch_bounds__(256, 2) void attn_k() {
    extern __shared__ __align__(16) __half smh[];
    const uint32_t sb = smem_u32(smh);

    const int tid = threadIdx.x;
    const int lane = tid & 31;
    const int wid = tid >> 5;
    const int g = lane >> 2;
    const int t = lane & 3;
    const int bh = blockIdx.y;
    const int bb = bh >> 4;
    const int hh = bh & 15;
    const int q0 = blockIdx.x * 128;

    const size_t hb = (size_t)(bb * NH + hh) * NT * 64;

    // Load Q tile into smem
#pragma unroll
    for (int i = 0; i < 4; i++) {
        int idx = i * 256 + tid;
        int r = idx >> 3, c = idx & 7;
        int gr = q0 + r;
        float4 v = make_float4(0.f, 0.f, 0.f, 0.f);
        if (gr < NT) v = ((const float4*)(g_qf + hb + (size_t)gr * 64))[c];
        *(float4*)((char*)smh + QF_B + (r * AST + c * 8) * 2) = v;
    }

    auto issue_kv = [&](int kt, int buf) {
        const int k0 = kt * 64;
        const uint32_t bbs = sb + KV0_B + buf * KVSTG_B;
#pragma unroll
        for (int i = 0; i < 2; i++) {
            int idx = i * 256 + tid;
            int r = idx >> 3, c = idx & 7;
            int gr = k0 + r;
            int sz = (gr < NT) ? 16 : 0;
            int grc = (gr < NT) ? gr : (NT - 1);
            size_t go = hb + (size_t)grc * 64 + c * 8;
            uint32_t so = bbs + (uint32_t)((r * AST + c * 8) * 2);
            cp16z(so,       g_kf + go, sz);
            cp16z(so + V_B, g_vf + go, sz);
        }
    };

    issue_kv(0, 0);
    CP_COMMIT();
    issue_kv(1, 1);
    CP_COMMIT();
    CP_WAIT(1);        // kv stage 0 complete; stage 1 in flight
    __syncthreads();   // Q tile + kv0 visible to all

    // Hoist Q fragments to registers (loop-invariant)
    const uint32_t a_base = sb + QF_B + 2 * (uint32_t)((wid * 16 + (lane & 15)) * AST + ((lane >> 4) << 3));
    uint32_t qfr[4][4];
#pragma unroll
    for (int ds = 0; ds < 4; ds++) ldm4(qfr[ds], a_base + 2 * (uint32_t)(ds * 16));

    const uint32_t b_roff = (uint32_t)((lane & 7) + ((lane >> 4) << 3));
    const uint32_t b_coff = (uint32_t)(((lane >> 3) & 1) << 3);
    const uint32_t v_roff = (uint32_t)(lane & 15);
    const uint32_t v_coff = (uint32_t)((lane >> 4) << 3);

    float oacc[8][4];
#pragma unroll
    for (int nd = 0; nd < 8; nd++)
#pragma unroll
        for (int j = 0; j < 4; j++) oacc[nd][j] = 0.f;
    float lacc[4] = {0.f, 0.f, 0.f, 0.f};
    float m2[2] = {-1e30f, -1e30f};
    const uint32_t bones[2] = {ONES_H2, ONES_H2};

    // S = Q K^T for a given KV stage base (accumulates into sacc)
    float sacc[8][4];
    auto qk = [&](uint32_t kvb) {
#pragma unroll
        for (int ni = 0; ni < 8; ni++)
#pragma unroll
            for (int j = 0; j < 4; j++) sacc[ni][j] = 0.f;
#pragma unroll
        for (int ds = 0; ds < 4; ds++) {
#pragma unroll
            for (int ng = 0; ng < 4; ng++) {
                uint32_t k4[4];
                uint32_t be = 2 * (uint32_t)((ng * 16 + b_roff) * AST + ds * 16 + b_coff);
                ldm4(k4, kvb + be);
                mma16816h(sacc[2 * ng],     qfr[ds], k4);
                mma16816h(sacc[2 * ng + 1], qfr[ds], k4 + 2);
            }
        }
    };

    // Prologue: S for stage 0
    qk(sb + KV0_B);

#pragma unroll 1
    for (int kt = 0; kt < 25; kt++) {
        const int k0 = kt * 64;

        // --- softmax on sacc (holds S for stage kt) ---
        if (k0 + 64 > NT) {
#pragma unroll
            for (int ni = 0; ni < 8; ni++) {
                int c0 = k0 + 8 * ni + 2 * t;
                if (c0 >= NT)     { sacc[ni][0] = -1e30f; sacc[ni][2] = -1e30f; }
                if (c0 + 1 >= NT) { sacc[ni][1] = -1e30f; sacc[ni][3] = -1e30f; }
            }
        }
#pragma unroll
        for (int h2 = 0; h2 < 2; h2++) {
            float mx = -1e30f;
#pragma unroll
            for (int ni = 0; ni < 8; ni++)
                mx = fmaxf(mx, fmaxf(sacc[ni][2 * h2], sacc[ni][2 * h2 + 1]));
            mx = fmaxf(mx, __shfl_xor_sync(0xffffffffu, mx, 1));
            mx = fmaxf(mx, __shfl_xor_sync(0xffffffffu, mx, 2));
            float mn = fmaxf(m2[h2], mx);
            float corr = ex2(m2[h2] - mn);
            m2[h2] = mn;
            lacc[2 * h2]     *= corr;
            lacc[2 * h2 + 1] *= corr;
#pragma unroll
            for (int nd = 0; nd < 8; nd++) {
                oacc[nd][2 * h2] *= corr;
                oacc[nd][2 * h2 + 1] *= corr;
            }
        }
        const float mn0 = m2[0], mn1 = m2[1];

        // Build ALL P fragments now (frees sacc for the next stage's S)
        uint32_t ph[4][4];
#pragma unroll
        for (int kc = 0; kc < 4; kc++) {
            ph[kc][0] = ex2h2(pack_h2(sacc[2 * kc][0] - mn0, sacc[2 * kc][1] - mn0));
            ph[kc][1] = ex2h2(pack_h2(sacc[2 * kc][2] - mn1, sacc[2 * kc][3] - mn1));
            ph[kc][2] = ex2h2(pack_h2(sacc[2 * kc + 1][0] - mn0, sacc[2 * kc + 1][1] - mn0));
            ph[kc][3] = ex2h2(pack_h2(sacc[2 * kc + 1][2] - mn1, sacc[2 * kc + 1][3] - mn1));
        }

        const uint32_t kvb_cur = sb + KV0_B + (kt % 3) * KVSTG_B;

        // --- pipelined S for stage kt+1 (independent of softmax output) ---
        if (kt + 1 < 25) {
            CP_WAIT(0);              // kv(kt+1) complete (only outstanding group)
            __syncthreads();         // visible to all; all threads past iter kt-1 reads
            if (kt + 2 < 25) {
                issue_kv(kt + 2, (kt + 2) % 3);   // buf (kt+2)%3 == (kt-1)%3: safe after barrier
                CP_COMMIT();
            }
            qk(sb + KV0_B + ((kt + 1) % 3) * KVSTG_B);
        }

        // --- O += P V; l += P * ones (stage kt) ---
#pragma unroll
        for (int kc = 0; kc < 4; kc++) {
            mma16816h(lacc, ph[kc], bones);
#pragma unroll
            for (int dg = 0; dg < 4; dg++) {
                uint32_t v4[4];
                uint32_t ve = 2 * (uint32_t)((kc * 16 + v_roff) * AST + dg * 16 + v_coff);
                ldm4t(v4, kvb_cur + V_B + ve);
                mma16816h(oacc[2 * dg],     ph[kc], v4);
                mma16816h(oacc[2 * dg + 1], ph[kc], v4 + 2);
            }
        }
    }

    // Normalize, store fp16 to [B*N][C].  l for row of h2 = lacc[2*h2] (all lanes)
#pragma unroll
    for (int h2 = 0; h2 < 2; h2++) {
        int r = q0 + wid * 16 + g + 8 * h2;
        if (r < NT) {
            float inv = 1.0f / lacc[2 * h2];
            size_t ob = (size_t)(bb * NT + r) * CC + hh * 64;
#pragma unroll
            for (int nd = 0; nd < 8; nd++) {
                int col = 8 * nd + 2 * t;
                *(uint32_t*)&g_of[ob + col] =
                    pack_h2(oacc[nd][2 * h2] * inv, oacc[nd][2 * h2 + 1] * inv);
            }
        }
    }
}

// ---------------------------------------------------------------------------
extern "C" void kernel_launch(void* const* d_in, const int* in_sizes, int n_in,
                              void* d_out, int out_size) {
    (void)in_sizes; (void)n_in; (void)out_size;
    const float* x = (const float*)d_in[0];
    const float* wqkv = (const float*)d_in[1];
    const float* wproj = (const float*)d_in[2];
    const float* bproj = (const float*)d_in[3];
    float* out = (float*)d_out;

    cudaFuncSetAttribute(attn_k, cudaFuncAttributeMaxDynamicSharedMemorySize, ATTN_SMEM);
    cudaFuncSetAttribute(gemm_mma<0>, cudaFuncAttributeMaxDynamicSharedMemorySize, GEMM_SMEM);
    cudaFuncSetAttribute(gemm_mma<1>, cudaFuncAttributeMaxDynamicSharedMemorySize, GEMM_SMEM);

    rope_tab_k<<<(NT * 60 + 255) / 256, 256>>>();
    conv_all_k<<<2960, 256>>>(x, wqkv, wproj);

    gemm_mma<0><<<dim3(24, 49), 256, GEMM_SMEM>>>(nullptr, nullptr);
    attn_k<<<dim3(13, 64), 256, ATTN_SMEM>>>();
    gemm_mma<1><<<dim3(8, 49), 256, GEMM_SMEM>>>(out, bproj);
}

// round 17
// speedup vs baseline: 1.0892x; 1.0892x over previous
#include <cuda_runtime.h>
#include <cuda_bf16.h>
#include <cuda_fp16.h>
#include <cstdint>

// Problem constants
#define BB 4
#define NT 1568
#define NH 16
#define HD 64
#define CC 1024
#define MROWS (BB * NT)          // 6272

// ---------------------------------------------------------------------------
// Scratch (device globals — no allocations allowed)
// ---------------------------------------------------------------------------
static __device__ __align__(16) float g_ctab[NT * 60];
static __device__ __align__(16) float g_stab[NT * 60];
static __device__ __align__(16) __half g_xf[MROWS * CC];
static __device__ __align__(16) __half g_wqf[3 * CC * CC];
static __device__ __align__(16) __half g_wpf[CC * CC];
#define QKVN (BB * NH * NT * HD)
static __device__ __align__(16) __half g_qf[QKVN], g_kf[QKVN], g_vf[QKVN];
static __device__ __align__(16) __half g_of[MROWS * CC];

#define LOG2E 1.44269504088896340736f

// ---------------------------------------------------------------------------
// Baseline-PTX helpers (plain sm_100 target)
// ---------------------------------------------------------------------------
__device__ __forceinline__ uint32_t smem_u32(const void* p) {
    uint32_t a;
    asm("{ .reg .u64 t; cvta.to.shared.u64 t, %1; cvt.u32.u64 %0, t; }" : "=r"(a) : "l"(p));
    return a;
}
__device__ __forceinline__ void ldm4(uint32_t* r, uint32_t addr) {
    asm volatile("ldmatrix.sync.aligned.m8n8.x4.shared.b16 {%0,%1,%2,%3}, [%4];"
                 : "=r"(r[0]), "=r"(r[1]), "=r"(r[2]), "=r"(r[3]) : "r"(addr));
}
__device__ __forceinline__ void ldm4t(uint32_t* r, uint32_t addr) {
    asm volatile("ldmatrix.sync.aligned.m8n8.x4.trans.shared.b16 {%0,%1,%2,%3}, [%4];"
                 : "=r"(r[0]), "=r"(r[1]), "=r"(r[2]), "=r"(r[3]) : "r"(addr));
}
__device__ __forceinline__ void mma16816h(float* c, const uint32_t* a, const uint32_t* b) {
    asm volatile(
        "mma.sync.aligned.m16n8k16.row.col.f32.f16.f16.f32 "
        "{%0,%1,%2,%3}, {%4,%5,%6,%7}, {%8,%9}, {%0,%1,%2,%3};"
        : "+f"(c[0]), "+f"(c[1]), "+f"(c[2]), "+f"(c[3])
        : "r"(a[0]), "r"(a[1]), "r"(a[2]), "r"(a[3]), "r"(b[0]), "r"(b[1]));
}
__device__ __forceinline__ void cp16(uint32_t s, const void* g) {
    asm volatile("cp.async.cg.shared.global [%0], [%1], 16;" :: "r"(s), "l"(g));
}
__device__ __forceinline__ void cp16z(uint32_t s, const void* g, int sz) {
    asm volatile("cp.async.cg.shared.global [%0], [%1], 16, %2;" :: "r"(s), "l"(g), "r"(sz));
}
#define CP_COMMIT() asm volatile("cp.async.commit_group;" ::: "memory")
#define CP_WAIT(n)  asm volatile("cp.async.wait_group %0;" :: "n"(n) : "memory")

__device__ __forceinline__ uint32_t pack_h2(float a, float b) {
    __half2 v = __floats2half2_rn(a, b);
    return *(uint32_t*)&v;
}
__device__ __forceinline__ float ex2(float x) {
    float y;
    asm("ex2.approx.f32 %0, %1;" : "=f"(y) : "f"(x));
    return y;
}

// ---------------------------------------------------------------------------
// RoPE table (validated R4/R6)
// ---------------------------------------------------------------------------
__global__ void rope_tab_k() {
    int i = blockIdx.x * 256 + threadIdx.x;
    if (i >= NT * 60) return;
    int n = i / 60;
    int d = i - n * 60;
    int axis = d / 20;
    int fi = (d % 20) % 10;
    int fr = n / 196;
    int inf = n - fr * 196;
    int hh = inf / 14;
    int ww = inf - hh * 14;
    float pos = (axis == 0) ? (float)fr : ((axis == 1) ? (float)hh : (float)ww);
    float omega = 1.0f / powf(10000.0f, (float)fi * 0.1f);
    g_ctab[i] = cosf(pos * omega);
    g_stab[i] = sinf(pos * omega);
}

// ---------------------------------------------------------------------------
// Fused fp32 -> fp16 conversion of x, Wqkv, Wproj in one launch (grid-stride)
// ---------------------------------------------------------------------------
#define N4X (MROWS * CC / 4)       // 1605632
#define N4W (3 * CC * CC / 4)      //  786432
#define N4P (CC * CC / 4)          //  262144
#define N4ALL (N4X + N4W + N4P)

__global__ void conv_all_k(const float* __restrict__ x,
                           const float* __restrict__ wq,
                           const float* __restrict__ wp) {
    for (int i = blockIdx.x * 256 + threadIdx.x; i < N4ALL; i += gridDim.x * 256) {
        const float* s;
        __half* d;
        int j = i;
        if (j < N4X) { s = x; d = g_xf; }
        else if (j < N4X + N4W) { j -= N4X; s = wq; d = g_wqf; }
        else { j -= N4X + N4W; s = wp; d = g_wpf; }
        float4 v = ((const float4*)s)[j];
        ((uint32_t*)d)[2 * j]     = pack_h2(v.x, v.y);
        ((uint32_t*)d)[2 * j + 1] = pack_h2(v.z, v.w);
    }
}

// ---------------------------------------------------------------------------
// mma.sync fp16 GEMM, cp.async double buffer, BK=64 (16 stages: half the
// barriers of the BK=32 version, 64 uninterrupted HMMA per warp per stage).
// Smem row stride 72 halves (144 B) — the bank-conflict-free pattern
// validated in attn_k since R7.
// EPI 0: QKV + RoPE -> fp16 q/k/v (q pre-scaled 0.125*log2e). grid 24x49
// EPI 1: out-projection + bias -> Cout.                       grid  8x49
// ---------------------------------------------------------------------------
#define GAST 72
#define TILE_B (128 * GAST * 2)      // 18432 B per operand tile
#define STG_B (2 * TILE_B)           // A + B per stage = 36864 B
#define OFF_A 0
#define OFF_B (TILE_B)
#define GEMM_SMEM (2 * STG_B)        // 73728 B

template <int EPI>
__global__ __launch_bounds__(256, 2) void gemm_mma(
    float* __restrict__ Cout, const float* __restrict__ bias)
{
    extern __shared__ __align__(16) char sm[];
    const uint32_t sb = smem_u32(sm);

    const int tid = threadIdx.x;
    const int lane = tid & 31;
    const int wid = tid >> 5;
    const int wm = wid & 3;
    const int wn = wid >> 2;
    const int bx = blockIdx.x;
    const int by = blockIdx.y;

    const __half* Ag = (EPI == 0) ? g_xf : g_of;
    const __half* Bg = (EPI == 0) ? g_wqf : g_wpf;

    float acc[2][8][4];
#pragma unroll
    for (int mi = 0; mi < 2; mi++)
#pragma unroll
        for (int ni = 0; ni < 8; ni++)
#pragma unroll
            for (int j = 0; j < 4; j++) acc[mi][ni][j] = 0.0f;

    const int lrow = tid >> 3;       // 0..31 step over rows (x4 iters -> 128)
    const int lch = tid & 7;         // 16B chunk along K (8 chunks = 64 halves)
    const uint32_t a_off = (uint32_t)(((wm * 32 + (lane & 15)) * GAST + ((lane >> 4) << 3)) * 2);
    const uint32_t b_off = (uint32_t)(((wn * 64 + (lane & 7) + ((lane >> 4) << 3)) * GAST +
                                      (((lane >> 3) & 1) << 3)) * 2);

    auto issue_tile = [&](int s, int buf) {
        const int k0 = s * 64;
        const uint32_t bbs = sb + buf * STG_B;
#pragma unroll
        for (int i = 0; i < 4; i++) {
            int r = lrow + i * 32;
            size_t ga = (size_t)(by * 128 + r) * 1024 + k0 + lch * 8;
            size_t gb = (size_t)(bx * 128 + r) * 1024 + k0 + lch * 8;
            uint32_t so = bbs + (uint32_t)((r * GAST + lch * 8) * 2);
            cp16(so + OFF_A, Ag + ga);
            cp16(so + OFF_B, Bg + gb);
        }
    };

    issue_tile(0, 0);
    CP_COMMIT();

#pragma unroll 1
    for (int s = 0; s < 16; s++) {
        CP_WAIT(0);
        __syncthreads();             // stage-s data visible; all threads done with s-1
        if (s + 1 < 16) {
            issue_tile(s + 1, (s + 1) & 1);   // overlaps compute of stage s
            CP_COMMIT();
        }

        const uint32_t bbs = sb + (s & 1) * STG_B;
#pragma unroll
        for (int ks = 0; ks < 4; ks++) {
            const uint32_t kb = (uint32_t)(ks * 32);   // 16 halves along K
            uint32_t af[2][4];
            ldm4(af[0], bbs + OFF_A + a_off + kb);
            ldm4(af[1], bbs + OFF_A + a_off + kb + 16 * GAST * 2);
#pragma unroll
            for (int np = 0; np < 4; np++) {
                uint32_t bf[4];
                ldm4(bf, bbs + OFF_B + b_off + kb + np * 16 * GAST * 2);
#pragma unroll
                for (int mi = 0; mi < 2; mi++) {
                    mma16816h(acc[mi][2 * np],     af[mi], bf);
                    mma16816h(acc[mi][2 * np + 1], af[mi], bf + 2);
                }
            }
        }
    }

    const int g = lane >> 2;
    const int t = lane & 3;
#pragma unroll
    for (int mi = 0; mi < 2; mi++) {
#pragma unroll
        for (int ni = 0; ni < 8; ni++) {
#pragma unroll
            for (int half = 0; half < 2; half++) {
                int rr = wm * 32 + mi * 16 + g + half * 8;
                int o = bx * 128 + wn * 64 + ni * 8 + 2 * t;
                float e = acc[mi][ni][2 * half];
                float oo = acc[mi][ni][2 * half + 1];
                int m = by * 128 + rr;
                if (EPI == 0) {
                    int b = m / NT;
                    int n = m - b * NT;
                    int nb = n * 60;
                    int sidx = o >> 10;
                    int hd = (o & 1023) >> 6;
                    int d = o & 63;
                    float oe = e, of = oo;
                    if (sidx < 2 && d < 60) {
                        float c0 = g_ctab[nb + d],     s0 = g_stab[nb + d];
                        float c1 = g_ctab[nb + d + 1], s1 = g_stab[nb + d + 1];
                        oe = fmaf(e, c0, -oo * s0);
                        of = fmaf(oo, c1, e * s1);
                    }
                    if (sidx == 0) { oe *= 0.125f * LOG2E; of *= 0.125f * LOG2E; }
                    __half* df = (sidx == 0) ? g_qf : ((sidx == 1) ? g_kf : g_vf);
                    size_t base = ((size_t)((b * NH + hd) * NT + n)) * 64 + d;
                    *(uint32_t*)&df[base] = pack_h2(oe, of);
                } else {
                    float2 bv = *(const float2*)&bias[o];
                    *(float2*)&Cout[(size_t)m * CC + o] = make_float2(e + bv.x, oo + bv.y);
                }
            }
        }
    }
}

// ---------------------------------------------------------------------------
// fp16 tensor-core flash attention — exact R13-measured form (157 us):
// Q fragments register-resident; one sync per KV stage; base-2 softmax with
// fp32 ex2; shfl row-sums.  grid (13 q-tiles, 64 bh). BQ=128, BK=64.
// ---------------------------------------------------------------------------
#define AST 72
#define QF_B 0
#define KV0_B (128 * AST * 2)            // 18432
#define KVSTG_B (2 * 64 * AST * 2)       // 18432
#define V_B (64 * AST * 2)               // 9216
#define ATTN_SMEM (KV0_B + 2 * KVSTG_B)  // 55296 bytes

__global__ __launch_bounds__(256, 2) void attn_k() {
    extern __shared__ __align__(16) __half smh[];
    const uint32_t sb = smem_u32(smh);

    const int tid = threadIdx.x;
    const int lane = tid & 31;
    const int wid = tid >> 5;
    const int g = lane >> 2;
    const int t = lane & 3;
    const int bh = blockIdx.y;
    const int bb = bh >> 4;
    const int hh = bh & 15;
    const int q0 = blockIdx.x * 128;

    const size_t hb = (size_t)(bb * NH + hh) * NT * 64;

    // Load Q tile into smem
#pragma unroll
    for (int i = 0; i < 4; i++) {
        int idx = i * 256 + tid;
        int r = idx >> 3, c = idx & 7;
        int gr = q0 + r;
        float4 v = make_float4(0.f, 0.f, 0.f, 0.f);
        if (gr < NT) v = ((const float4*)(g_qf + hb + (size_t)gr * 64))[c];
        *(float4*)((char*)smh + QF_B + (r * AST + c * 8) * 2) = v;
    }

    auto issue_kv = [&](int kt, int buf) {
        const int k0 = kt * 64;
        const uint32_t bbs = sb + KV0_B + buf * KVSTG_B;
#pragma unroll
        for (int i = 0; i < 2; i++) {
            int idx = i * 256 + tid;
            int r = idx >> 3, c = idx & 7;
            int gr = k0 + r;
            int sz = (gr < NT) ? 16 : 0;
            int grc = (gr < NT) ? gr : (NT - 1);
            size_t go = hb + (size_t)grc * 64 + c * 8;
            uint32_t so = bbs + (uint32_t)((r * AST + c * 8) * 2);
            cp16z(so,       g_kf + go, sz);
            cp16z(so + V_B, g_vf + go, sz);
        }
    };

    issue_kv(0, 0);
    CP_COMMIT();
    __syncthreads();   // Q tile stores visible

    // Hoist Q fragments to registers (loop-invariant)
    const uint32_t a_base = sb + QF_B + 2 * (uint32_t)((wid * 16 + (lane & 15)) * AST + ((lane >> 4) << 3));
    uint32_t qfr[4][4];
#pragma unroll
    for (int ds = 0; ds < 4; ds++) ldm4(qfr[ds], a_base + 2 * (uint32_t)(ds * 16));

    const uint32_t b_roff = (uint32_t)((lane & 7) + ((lane >> 4) << 3));
    const uint32_t b_coff = (uint32_t)(((lane >> 3) & 1) << 3);
    const uint32_t v_roff = (uint32_t)(lane & 15);
    const uint32_t v_coff = (uint32_t)((lane >> 4) << 3);

    float oacc[8][4];
#pragma unroll
    for (int nd = 0; nd < 8; nd++)
#pragma unroll
        for (int j = 0; j < 4; j++) oacc[nd][j] = 0.f;
    float m2[2] = {-1e30f, -1e30f};
    float l2[2] = {0.f, 0.f};

#pragma unroll 1
    for (int kt = 0; kt < 25; kt++) {
        const int k0 = kt * 64;
        CP_WAIT(0);
        __syncthreads();             // KV stage visible; all threads done with kt-1
        if (kt + 1 < 25) {
            issue_kv(kt + 1, (kt + 1) & 1);   // overlaps compute of stage kt
            CP_COMMIT();
        }
        const uint32_t kvb = sb + KV0_B + (kt & 1) * KVSTG_B;

        // S = Q K^T (log2-scaled logits; q carries 0.125*log2e)
        float sacc[8][4];
#pragma unroll
        for (int ni = 0; ni < 8; ni++)
#pragma unroll
            for (int j = 0; j < 4; j++) sacc[ni][j] = 0.f;

#pragma unroll
        for (int ds = 0; ds < 4; ds++) {
#pragma unroll
            for (int ng = 0; ng < 4; ng++) {
                uint32_t k4[4];
                uint32_t be = 2 * (uint32_t)((ng * 16 + b_roff) * AST + ds * 16 + b_coff);
                ldm4(k4, kvb + be);
                mma16816h(sacc[2 * ng],     qfr[ds], k4);
                mma16816h(sacc[2 * ng + 1], qfr[ds], k4 + 2);
            }
        }

        // Online softmax (base 2)
        if (k0 + 64 > NT) {
#pragma unroll
            for (int ni = 0; ni < 8; ni++) {
                int c0 = k0 + 8 * ni + 2 * t;
                if (c0 >= NT)     { sacc[ni][0] = -1e30f; sacc[ni][2] = -1e30f; }
                if (c0 + 1 >= NT) { sacc[ni][1] = -1e30f; sacc[ni][3] = -1e30f; }
            }
        }
#pragma unroll
        for (int h2 = 0; h2 < 2; h2++) {
            float mx = -1e30f;
#pragma unroll
            for (int ni = 0; ni < 8; ni++)
                mx = fmaxf(mx, fmaxf(sacc[ni][2 * h2], sacc[ni][2 * h2 + 1]));
            mx = fmaxf(mx, __shfl_xor_sync(0xffffffffu, mx, 1));
            mx = fmaxf(mx, __shfl_xor_sync(0xffffffffu, mx, 2));
            float mn = fmaxf(m2[h2], mx);
            float corr = ex2(m2[h2] - mn);
            m2[h2] = mn;
            float rs = 0.f;
#pragma unroll
            for (int ni = 0; ni < 8; ni++) {
                float p0 = ex2(sacc[ni][2 * h2] - mn);
                float p1 = ex2(sacc[ni][2 * h2 + 1] - mn);
                sacc[ni][2 * h2] = p0;
                sacc[ni][2 * h2 + 1] = p1;
                rs += p0 + p1;
            }
            rs += __shfl_xor_sync(0xffffffffu, rs, 1);
            rs += __shfl_xor_sync(0xffffffffu, rs, 2);
            l2[h2] = l2[h2] * corr + rs;
#pragma unroll
            for (int nd = 0; nd < 8; nd++) {
                oacc[nd][2 * h2] *= corr;
                oacc[nd][2 * h2 + 1] *= corr;
            }
        }

        // O += P V
#pragma unroll
        for (int kc = 0; kc < 4; kc++) {
            uint32_t ph[4];
            ph[0] = pack_h2(sacc[2 * kc][0], sacc[2 * kc][1]);
            ph[1] = pack_h2(sacc[2 * kc][2], sacc[2 * kc][3]);
            ph[2] = pack_h2(sacc[2 * kc + 1][0], sacc[2 * kc + 1][1]);
            ph[3] = pack_h2(sacc[2 * kc + 1][2], sacc[2 * kc + 1][3]);
#pragma unroll
            for (int dg = 0; dg < 4; dg++) {
                uint32_t v4[4];
                uint32_t ve = 2 * (uint32_t)((kc * 16 + v_roff) * AST + dg * 16 + v_coff);
                ldm4t(v4, kvb + V_B + ve);
                mma16816h(oacc[2 * dg],     ph, v4);
                mma16816h(oacc[2 * dg + 1], ph, v4 + 2);
            }
        }
    }

    // Normalize, store fp16 to [B*N][C]
#pragma unroll
    for (int h2 = 0; h2 < 2; h2++) {
        int r = q0 + wid * 16 + g + 8 * h2;
        if (r < NT) {
            float inv = 1.0f / l2[h2];
            size_t ob = (size_t)(bb * NT + r) * CC + hh * 64;
#pragma unroll
            for (int nd = 0; nd < 8; nd++) {
                int col = 8 * nd + 2 * t;
                *(uint32_t*)&g_of[ob + col] =
                    pack_h2(oacc[nd][2 * h2] * inv, oacc[nd][2 * h2 + 1] * inv);
            }
        }
    }
}

// ---------------------------------------------------------------------------
extern "C" void kernel_launch(void* const* d_in, const int* in_sizes, int n_in,
                              void* d_out, int out_size) {
    (void)in_sizes; (void)n_in; (void)out_size;
    const float* x = (const float*)d_in[0];
    const float* wqkv = (const float*)d_in[1];
    const float* wproj = (const float*)d_in[2];
    const float* bproj = (const float*)d_in[3];
    float* out = (float*)d_out;

    cudaFuncSetAttribute(attn_k, cudaFuncAttributeMaxDynamicSharedMemorySize, ATTN_SMEM);
    cudaFuncSetAttribute(gemm_mma<0>, cudaFuncAttributeMaxDynamicSharedMemorySize, GEMM_SMEM);
    cudaFuncSetAttribute(gemm_mma<1>, cudaFuncAttributeMaxDynamicSharedMemorySize, GEMM_SMEM);

    rope_tab_k<<<(NT * 60 + 255) / 256, 256>>>();
    conv_all_k<<<2960, 256>>>(x, wqkv, wproj);

    gemm_mma<0><<<dim3(24, 49), 256, GEMM_SMEM>>>(nullptr, nullptr);
    attn_k<<<dim3(13, 64), 256, ATTN_SMEM>>>();
    gemm_mma<1><<<dim3(8, 49), 256, GEMM_SMEM>>>(out, bproj);
}